// round 5
// baseline (speedup 1.0000x reference)
#include <cuda_runtime.h>
#include <cuda_bf16.h>
#include <math.h>
#include <stdint.h>

// Problem constants
#define T_TOK 49152          // B*S*N = 2*24*1024
#define HID   512
#define NEXP  8
#define MOEI  1024
#define SHI   2048
#define NSLOT (2 * T_TOK)    // top-2 -> exactly 2 slots per token

// ---------------------------------------------------------------------------
// Scratch (static __device__ arrays; no allocation anywhere)
// ---------------------------------------------------------------------------
__device__ float g_bufA[100663296];             // 2T*1024 == T*2048  (g / h)
__device__ float g_bufB[100663296];             // (spare)
__device__ float g_y  [(size_t)NSLOT * HID];    // per-slot expert output
__device__ float g_ys [(size_t)T_TOK * HID];    // shared-expert output
__device__ int   g_topk_idx[NSLOT];
__device__ float g_topk_w [NSLOT];
__device__ float g_sig    [T_TOK];
__device__ int   g_counts [NEXP];
__device__ int   g_offsets[NEXP];
__device__ int   g_cursor [NEXP];
__device__ int   g_slot_token[NSLOT];           // slot -> token
__device__ int   g_slot_of   [NSLOT];           // (token,k) -> slot

// ---------------------------------------------------------------------------
// helpers: tf32 rounding + mma
// ---------------------------------------------------------------------------
__device__ __forceinline__ uint32_t f2tf32(float x) {
    uint32_t r;
    asm("cvt.rna.tf32.f32 %0, %1;" : "=r"(r) : "f"(x));
    return r;
}

__device__ __forceinline__ void mma_tf32(float* c, const uint32_t* a,
                                         uint32_t b0, uint32_t b1) {
    asm volatile(
        "mma.sync.aligned.m16n8k8.row.col.f32.tf32.tf32.f32 "
        "{%0,%1,%2,%3},{%4,%5,%6,%7},{%8,%9},{%0,%1,%2,%3};"
        : "+f"(c[0]), "+f"(c[1]), "+f"(c[2]), "+f"(c[3])
        : "r"(a[0]), "r"(a[1]), "r"(a[2]), "r"(a[3]), "r"(b0), "r"(b1));
}

__device__ __forceinline__ float silu(float x) {
    return x * (1.f / (1.f + __expf(-x)));
}

// ---------------------------------------------------------------------------
// 0) zero counters
// ---------------------------------------------------------------------------
__global__ void init_kernel() {
    int i = threadIdx.x;
    if (i < NEXP) { g_counts[i] = 0; g_cursor[i] = 0; }
}

// ---------------------------------------------------------------------------
// 1) router: logits, softmax, top-2, sigmoid(x@sgate); count experts
// ---------------------------------------------------------------------------
__global__ void __launch_bounds__(256) router_kernel(
    const float* __restrict__ x, const float* __restrict__ gw,
    const float* __restrict__ sg, float* __restrict__ logits_out)
{
    __shared__ float s_gw[HID * NEXP];
    __shared__ float s_sg[HID];
    for (int i = threadIdx.x; i < HID * NEXP; i += 256) s_gw[i] = gw[i];
    for (int i = threadIdx.x; i < HID; i += 256) s_sg[i] = sg[i];
    __syncthreads();

    int warp = threadIdx.x >> 5, lane = threadIdx.x & 31;
    int t = blockIdx.x * 8 + warp;
    const float* xr = x + (size_t)t * HID;

    float acc[NEXP];
#pragma unroll
    for (int e = 0; e < NEXP; e++) acc[e] = 0.f;
    float accs = 0.f;

#pragma unroll 4
    for (int i = 0; i < 16; i++) {
        int h = i * 32 + lane;
        float xv = xr[h];
#pragma unroll
        for (int e = 0; e < NEXP; e++) acc[e] += xv * s_gw[h * NEXP + e];
        accs += xv * s_sg[h];
    }
#pragma unroll
    for (int off = 16; off; off >>= 1) {
#pragma unroll
        for (int e = 0; e < NEXP; e++)
            acc[e] += __shfl_xor_sync(0xffffffff, acc[e], off);
        accs += __shfl_xor_sync(0xffffffff, accs, off);
    }

    if (lane == 0) {
        if (logits_out) {
#pragma unroll
            for (int e = 0; e < NEXP; e++) logits_out[(size_t)t * NEXP + e] = acc[e];
        }
        float m = acc[0];
#pragma unroll
        for (int e = 1; e < NEXP; e++) m = fmaxf(m, acc[e]);
        float p[NEXP], sum = 0.f;
#pragma unroll
        for (int e = 0; e < NEXP; e++) { p[e] = expf(acc[e] - m); sum += p[e]; }
        float inv = 1.f / sum;
#pragma unroll
        for (int e = 0; e < NEXP; e++) p[e] *= inv;

        int i1 = 0;
#pragma unroll
        for (int e = 1; e < NEXP; e++) if (p[e] > p[i1]) i1 = e;
        int i2 = (i1 == 0) ? 1 : 0;
#pragma unroll
        for (int e = 0; e < NEXP; e++) if (e != i1 && e != i2 && p[e] > p[i2]) i2 = e;

        g_topk_idx[2 * t]     = i1; g_topk_w[2 * t]     = p[i1];
        g_topk_idx[2 * t + 1] = i2; g_topk_w[2 * t + 1] = p[i2];
        atomicAdd(&g_counts[i1], 1);
        atomicAdd(&g_counts[i2], 1);
        g_sig[t] = 1.f / (1.f + expf(-accs));
    }
}

// ---------------------------------------------------------------------------
// 2) exclusive prefix over 8 counts
// ---------------------------------------------------------------------------
__global__ void prefix_kernel() {
    if (threadIdx.x == 0) {
        int s = 0;
        for (int e = 0; e < NEXP; e++) { g_offsets[e] = s; g_cursor[e] = s; s += g_counts[e]; }
    }
}

// ---------------------------------------------------------------------------
// 3) scatter tokens into per-expert slot lists
// ---------------------------------------------------------------------------
__global__ void scatter_kernel() {
    int t = blockIdx.x * 256 + threadIdx.x;
    if (t >= T_TOK) return;
#pragma unroll
    for (int k = 0; k < 2; k++) {
        int e = g_topk_idx[2 * t + k];
        int pos = atomicAdd(&g_cursor[e], 1);
        g_slot_token[pos] = t;
        g_slot_of[2 * t + k] = pos;
    }
}

// ---------------------------------------------------------------------------
// 4) tf32 tensor-core GEMM, 128x128 block tile, K-tile 32, 256 threads.
//    8 warps, each 64x32 via 4x4 grid of mma.sync.m16n8k8.tf32.
//    Register prefetch of next K-tile overlaps the mma stage.
//    Optional fused SwiGLU epilogue: C = silu(G) * U where U is the mma
//    result and G is read from gateBuf at the same (row, col).
// ---------------------------------------------------------------------------
__global__ void __launch_bounds__(256, 1) sgemm_tc_kernel(
    const float* __restrict__ A, const float* __restrict__ B, float* __restrict__ C,
    const float* __restrict__ gateBuf,
    int N, int K, long strideB, int Mfixed, int useCounts, int useGather)
{
    __shared__ float As[128][36];   // [m][k], padded
    __shared__ float Bs[32][136];   // [k][n], padded

    int e = blockIdx.z;
    int M, base;
    if (useCounts) { M = g_counts[e]; base = g_offsets[e]; }
    else           { M = Mfixed;      base = 0; }
    int row0 = blockIdx.y * 128;
    if (row0 >= M) return;
    int col0 = blockIdx.x * 128;
    const float* Bp = B + (size_t)e * strideB;

    int tid  = threadIdx.x;
    int lane = tid & 31;
    int wid  = tid >> 5;
    int wm   = (wid & 1) * 64;     // warp M offset within block tile
    int wn   = (wid >> 1) * 32;    // warp N offset

    // ---- global load lanes: 4 float4 of A + 4 float4 of B per thread ----
    const float* aptr[4];
#pragma unroll
    for (int j = 0; j < 4; j++) {
        int v = tid + j * 256;
        int r = v >> 3;
        int gr = row0 + r; if (gr > M - 1) gr = M - 1;
        long arow = useGather ? (long)g_slot_token[base + gr] : (long)(base + gr);
        aptr[j] = A + (size_t)arow * K + (v & 7) * 4;
    }
    const float* bptr[4];
#pragma unroll
    for (int j = 0; j < 4; j++) {
        int v = tid + j * 256;
        bptr[j] = Bp + (size_t)(v >> 5) * N + col0 + (v & 31) * 4;
    }

    float acc[4][4][4];
#pragma unroll
    for (int mi = 0; mi < 4; mi++)
#pragma unroll
        for (int ni = 0; ni < 4; ni++)
#pragma unroll
            for (int q = 0; q < 4; q++) acc[mi][ni][q] = 0.f;

    int nk = K >> 5;                // K-tiles of 32

    float4 sa[4], sb[4];
#pragma unroll
    for (int j = 0; j < 4; j++) { sa[j] = *(const float4*)aptr[j]; aptr[j] += 32; }
#pragma unroll
    for (int j = 0; j < 4; j++) { sb[j] = *(const float4*)bptr[j]; bptr[j] += (size_t)32 * N; }

    for (int kt = 0; kt < nk; kt++) {
#pragma unroll
        for (int j = 0; j < 4; j++) {
            int v = tid + j * 256;
            float* d = &As[v >> 3][(v & 7) * 4];
            d[0] = __uint_as_float(f2tf32(sa[j].x));
            d[1] = __uint_as_float(f2tf32(sa[j].y));
            d[2] = __uint_as_float(f2tf32(sa[j].z));
            d[3] = __uint_as_float(f2tf32(sa[j].w));
        }
#pragma unroll
        for (int j = 0; j < 4; j++) {
            int v = tid + j * 256;
            float* d = &Bs[v >> 5][(v & 31) * 4];
            d[0] = __uint_as_float(f2tf32(sb[j].x));
            d[1] = __uint_as_float(f2tf32(sb[j].y));
            d[2] = __uint_as_float(f2tf32(sb[j].z));
            d[3] = __uint_as_float(f2tf32(sb[j].w));
        }
        __syncthreads();

        if (kt + 1 < nk) {
#pragma unroll
            for (int j = 0; j < 4; j++) { sa[j] = *(const float4*)aptr[j]; aptr[j] += 32; }
#pragma unroll
            for (int j = 0; j < 4; j++) { sb[j] = *(const float4*)bptr[j]; bptr[j] += (size_t)32 * N; }
        }

#pragma unroll
        for (int ks = 0; ks < 4; ks++) {
            int k0 = ks * 8;
            uint32_t af[4][4];
#pragma unroll
            for (int mi = 0; mi < 4; mi++) {
                int r = wm + mi * 16 + (lane >> 2);
                int kc = k0 + (lane & 3);
                af[mi][0] = __float_as_uint(As[r][kc]);
                af[mi][1] = __float_as_uint(As[r + 8][kc]);
                af[mi][2] = __float_as_uint(As[r][kc + 4]);
                af[mi][3] = __float_as_uint(As[r + 8][kc + 4]);
            }
#pragma unroll
            for (int ni = 0; ni < 4; ni++) {
                int c = wn + ni * 8 + (lane >> 2);
                uint32_t b0 = __float_as_uint(Bs[k0 + (lane & 3)][c]);
                uint32_t b1 = __float_as_uint(Bs[k0 + 4 + (lane & 3)][c]);
#pragma unroll
                for (int mi = 0; mi < 4; mi++)
                    mma_tf32(acc[mi][ni], af[mi], b0, b1);
            }
        }
        __syncthreads();
    }

    // epilogue: c0,c1 at (row, 2*(lane&3)+{0,1}), c2,c3 at row+8
#pragma unroll
    for (int mi = 0; mi < 4; mi++) {
        int r0 = row0 + wm + mi * 16 + (lane >> 2);
        int r1 = r0 + 8;
#pragma unroll
        for (int ni = 0; ni < 4; ni++) {
            int c = col0 + wn + ni * 8 + (lane & 3) * 2;
            if (r0 < M) {
                size_t off = (size_t)(base + r0) * N + c;
                float v0 = acc[mi][ni][0], v1 = acc[mi][ni][1];
                if (gateBuf) {
                    float2 gv = *(const float2*)(gateBuf + off);
                    v0 *= silu(gv.x); v1 *= silu(gv.y);
                }
                float* p = C + off;
                p[0] = v0; p[1] = v1;
            }
            if (r1 < M) {
                size_t off = (size_t)(base + r1) * N + c;
                float v2 = acc[mi][ni][2], v3 = acc[mi][ni][3];
                if (gateBuf) {
                    float2 gv = *(const float2*)(gateBuf + off);
                    v2 *= silu(gv.x); v3 *= silu(gv.y);
                }
                float* p = C + off;
                p[0] = v2; p[1] = v3;
            }
        }
    }
}

// ---------------------------------------------------------------------------
// 6) combine: out[t] = w0*y[s0] + w1*y[s1] + sig[t]*ys[t]
// ---------------------------------------------------------------------------
__global__ void __launch_bounds__(128) combine_kernel(float* __restrict__ out)
{
    int t = blockIdx.x;
    int j = threadIdx.x;
    float w0 = g_topk_w[2 * t], w1 = g_topk_w[2 * t + 1];
    int   s0 = g_slot_of[2 * t], s1 = g_slot_of[2 * t + 1];
    float sg = g_sig[t];
    const float4* y4  = (const float4*)g_y;
    const float4* ys4 = (const float4*)g_ys;
    float4 a = y4[(size_t)s0 * 128 + j];
    float4 b = y4[(size_t)s1 * 128 + j];
    float4 c = ys4[(size_t)t * 128 + j];
    float4 r;
    r.x = w0 * a.x + w1 * b.x + sg * c.x;
    r.y = w0 * a.y + w1 * b.y + sg * c.y;
    r.z = w0 * a.z + w1 * b.z + sg * c.z;
    r.w = w0 * a.w + w1 * b.w + sg * c.w;
    ((float4*)out)[(size_t)t * 128 + j] = r;
}

// ---------------------------------------------------------------------------
// launch
// ---------------------------------------------------------------------------
extern "C" void kernel_launch(void* const* d_in, const int* in_sizes, int n_in,
                              void* d_out, int out_size)
{
    const float* x     = (const float*)d_in[0];
    const float* gate  = (const float*)d_in[1];
    const float* w1    = (const float*)d_in[2];
    const float* w2    = (const float*)d_in[3];
    const float* w3    = (const float*)d_in[4];
    const float* sw1   = (const float*)d_in[5];
    const float* sw2   = (const float*)d_in[6];
    const float* sw3   = (const float*)d_in[7];
    const float* sgate = (const float*)d_in[8];
    float* out = (float*)d_out;

    float* logits = nullptr;
    if ((size_t)out_size >= (size_t)T_TOK * HID + (size_t)T_TOK * NEXP)
        logits = out + (size_t)T_TOK * HID;

    float *bufA, *bufB, *ybuf, *ysbuf;
    cudaGetSymbolAddress((void**)&bufA,  g_bufA);
    cudaGetSymbolAddress((void**)&bufB,  g_bufB);
    cudaGetSymbolAddress((void**)&ybuf,  g_y);
    cudaGetSymbolAddress((void**)&ysbuf, g_ys);

    init_kernel<<<1, 32>>>();
    router_kernel<<<T_TOK / 8, 256>>>(x, gate, sgate, logits);
    prefix_kernel<<<1, 32>>>();
    scatter_kernel<<<T_TOK / 256, 256>>>();

    // MoE stage A: g = X_g @ w1[e] -> bufA
    sgemm_tc_kernel<<<dim3(MOEI / 128, T_TOK / 128, NEXP), 256>>>(
        x, w1, bufA, nullptr, MOEI, HID, (long)HID * MOEI, 0, 1, 1);
    // MoE stage A': u = X_g @ w3[e]; fused epilogue h = silu(g)*u -> bufA
    sgemm_tc_kernel<<<dim3(MOEI / 128, T_TOK / 128, NEXP), 256>>>(
        x, w3, bufA, bufA, MOEI, HID, (long)HID * MOEI, 0, 1, 1);
    // MoE stage B: y_slot = h @ w2[e]
    sgemm_tc_kernel<<<dim3(HID / 128, T_TOK / 128, NEXP), 256>>>(
        bufA, w2, ybuf, nullptr, HID, MOEI, (long)MOEI * HID, 0, 1, 0);

    // Shared expert (dense over all T tokens)
    sgemm_tc_kernel<<<dim3(SHI / 128, T_TOK / 128, 1), 256>>>(
        x, sw1, bufB, nullptr, SHI, HID, 0L, T_TOK, 0, 0);
    sgemm_tc_kernel<<<dim3(SHI / 128, T_TOK / 128, 1), 256>>>(
        x, sw3, bufB, bufB, SHI, HID, 0L, T_TOK, 0, 0);
    sgemm_tc_kernel<<<dim3(HID / 128, T_TOK / 128, 1), 256>>>(
        bufB, sw2, ysbuf, nullptr, HID, SHI, 0L, T_TOK, 0, 0);

    combine_kernel<<<T_TOK, 128>>>(out);
}

// round 7
// speedup vs baseline: 1.2219x; 1.2219x over previous
#include <cuda_runtime.h>
#include <cuda_bf16.h>
#include <math.h>
#include <stdint.h>

// Problem constants
#define T_TOK 49152          // B*S*N = 2*24*1024
#define HID   512
#define NEXP  8
#define MOEI  1024
#define SHI   2048
#define NSLOT (2 * T_TOK)    // top-2 -> exactly 2 slots per token

// ---------------------------------------------------------------------------
// Scratch (static __device__ arrays; no allocation anywhere)
// ---------------------------------------------------------------------------
__device__ float g_bufA[100663296];             // h for MoE (2T x MOEI)
__device__ float g_bufB[100663296];             // h for shared (T x SHI)
__device__ float g_y  [(size_t)NSLOT * HID];    // per-slot expert output
__device__ float g_ys [(size_t)T_TOK * HID];    // shared-expert output
__device__ int   g_topk_idx[NSLOT];
__device__ float g_topk_w [NSLOT];
__device__ float g_sig    [T_TOK];
__device__ int   g_counts [NEXP];
__device__ int   g_offsets[NEXP];
__device__ int   g_cursor [NEXP];
__device__ int   g_slot_token[NSLOT];           // slot -> token
__device__ int   g_slot_of   [NSLOT];           // (token,k) -> slot

// ---------------------------------------------------------------------------
// helpers
// ---------------------------------------------------------------------------
__device__ __forceinline__ uint32_t f2tf32(float x) {
    uint32_t r;
    asm("cvt.rna.tf32.f32 %0, %1;" : "=r"(r) : "f"(x));
    return r;
}

__device__ __forceinline__ void mma_tf32(float* c, const uint32_t* a,
                                         uint32_t b0, uint32_t b1) {
    asm volatile(
        "mma.sync.aligned.m16n8k8.row.col.f32.tf32.tf32.f32 "
        "{%0,%1,%2,%3},{%4,%5,%6,%7},{%8,%9},{%0,%1,%2,%3};"
        : "+f"(c[0]), "+f"(c[1]), "+f"(c[2]), "+f"(c[3])
        : "r"(a[0]), "r"(a[1]), "r"(a[2]), "r"(a[3]), "r"(b0), "r"(b1));
}

__device__ __forceinline__ float silu(float x) {
    return x * (1.f / (1.f + __expf(-x)));
}

// ---------------------------------------------------------------------------
// 0) zero counters
// ---------------------------------------------------------------------------
__global__ void init_kernel() {
    int i = threadIdx.x;
    if (i < NEXP) { g_counts[i] = 0; g_cursor[i] = 0; }
}

// ---------------------------------------------------------------------------
// 1) router: logits, softmax, top-2, sigmoid(x@sgate); count experts
// ---------------------------------------------------------------------------
__global__ void __launch_bounds__(256) router_kernel(
    const float* __restrict__ x, const float* __restrict__ gw,
    const float* __restrict__ sg, float* __restrict__ logits_out)
{
    __shared__ float s_gw[HID * NEXP];
    __shared__ float s_sg[HID];
    for (int i = threadIdx.x; i < HID * NEXP; i += 256) s_gw[i] = gw[i];
    for (int i = threadIdx.x; i < HID; i += 256) s_sg[i] = sg[i];
    __syncthreads();

    int warp = threadIdx.x >> 5, lane = threadIdx.x & 31;
    int t = blockIdx.x * 8 + warp;
    const float* xr = x + (size_t)t * HID;

    float acc[NEXP];
#pragma unroll
    for (int e = 0; e < NEXP; e++) acc[e] = 0.f;
    float accs = 0.f;

#pragma unroll 4
    for (int i = 0; i < 16; i++) {
        int h = i * 32 + lane;
        float xv = xr[h];
#pragma unroll
        for (int e = 0; e < NEXP; e++) acc[e] += xv * s_gw[h * NEXP + e];
        accs += xv * s_sg[h];
    }
#pragma unroll
    for (int off = 16; off; off >>= 1) {
#pragma unroll
        for (int e = 0; e < NEXP; e++)
            acc[e] += __shfl_xor_sync(0xffffffff, acc[e], off);
        accs += __shfl_xor_sync(0xffffffff, accs, off);
    }

    if (lane == 0) {
        if (logits_out) {
#pragma unroll
            for (int e = 0; e < NEXP; e++) logits_out[(size_t)t * NEXP + e] = acc[e];
        }
        float m = acc[0];
#pragma unroll
        for (int e = 1; e < NEXP; e++) m = fmaxf(m, acc[e]);
        float p[NEXP], sum = 0.f;
#pragma unroll
        for (int e = 0; e < NEXP; e++) { p[e] = expf(acc[e] - m); sum += p[e]; }
        float inv = 1.f / sum;
#pragma unroll
        for (int e = 0; e < NEXP; e++) p[e] *= inv;

        int i1 = 0;
#pragma unroll
        for (int e = 1; e < NEXP; e++) if (p[e] > p[i1]) i1 = e;
        int i2 = (i1 == 0) ? 1 : 0;
#pragma unroll
        for (int e = 0; e < NEXP; e++) if (e != i1 && e != i2 && p[e] > p[i2]) i2 = e;

        g_topk_idx[2 * t]     = i1; g_topk_w[2 * t]     = p[i1];
        g_topk_idx[2 * t + 1] = i2; g_topk_w[2 * t + 1] = p[i2];
        atomicAdd(&g_counts[i1], 1);
        atomicAdd(&g_counts[i2], 1);
        g_sig[t] = 1.f / (1.f + expf(-accs));
    }
}

// ---------------------------------------------------------------------------
// 2) exclusive prefix over 8 counts
// ---------------------------------------------------------------------------
__global__ void prefix_kernel() {
    if (threadIdx.x == 0) {
        int s = 0;
        for (int e = 0; e < NEXP; e++) { g_offsets[e] = s; g_cursor[e] = s; s += g_counts[e]; }
    }
}

// ---------------------------------------------------------------------------
// 3) scatter tokens into per-expert slot lists
// ---------------------------------------------------------------------------
__global__ void scatter_kernel() {
    int t = blockIdx.x * 256 + threadIdx.x;
    if (t >= T_TOK) return;
#pragma unroll
    for (int k = 0; k < 2; k++) {
        int e = g_topk_idx[2 * t + k];
        int pos = atomicAdd(&g_cursor[e], 1);
        g_slot_token[pos] = t;
        g_slot_of[2 * t + k] = pos;
    }
}

// ---------------------------------------------------------------------------
// 4a) dual tf32 GEMM + in-register SwiGLU:
//     C = silu(A@B1) * (A@B3).  Block 128x64, 8 warps as 4(m)x2(n),
//     warp tile 32x32, dual accumulators. A tile loaded once, shared.
// ---------------------------------------------------------------------------
__global__ void __launch_bounds__(256, 1) dual_swiglu_kernel(
    const float* __restrict__ A, const float* __restrict__ B1,
    const float* __restrict__ B3, float* __restrict__ C,
    int N, int K, long strideB, int Mfixed, int useCounts, int useGather)
{
    __shared__ float As[128][36];   // [m][k], padded
    __shared__ float B1s[32][72];   // [k][n], padded 64+8
    __shared__ float B3s[32][72];

    int e = blockIdx.z;
    int M, base;
    if (useCounts) { M = g_counts[e]; base = g_offsets[e]; }
    else           { M = Mfixed;      base = 0; }
    int row0 = blockIdx.y * 128;
    if (row0 >= M) return;
    int col0 = blockIdx.x * 64;
    const float* B1p = B1 + (size_t)e * strideB;
    const float* B3p = B3 + (size_t)e * strideB;

    int tid  = threadIdx.x;
    int lane = tid & 31;
    int wid  = tid >> 5;
    int wm   = (wid >> 1) * 32;    // 4 m-warps
    int wn   = (wid & 1) * 32;     // 2 n-warps

    // A: 4 float4 per thread: v -> row=v>>3 (0..127), f4=v&7
    const float* aptr[4];
#pragma unroll
    for (int j = 0; j < 4; j++) {
        int v = tid + j * 256;
        int r = v >> 3;
        int gr = row0 + r; if (gr > M - 1) gr = M - 1;
        long arow = useGather ? (long)g_slot_token[base + gr] : (long)(base + gr);
        aptr[j] = A + (size_t)arow * K + (v & 7) * 4;
    }
    // B: 2 float4 per thread per matrix: v -> krow=v>>4 (0..31), colq=v&15
    const float* b1ptr[2]; const float* b3ptr[2];
#pragma unroll
    for (int j = 0; j < 2; j++) {
        int v = tid + j * 256;
        size_t off = (size_t)(v >> 4) * N + col0 + (v & 15) * 4;
        b1ptr[j] = B1p + off;
        b3ptr[j] = B3p + off;
    }

    float accg[2][4][4], accu[2][4][4];
#pragma unroll
    for (int mi = 0; mi < 2; mi++)
#pragma unroll
        for (int ni = 0; ni < 4; ni++)
#pragma unroll
            for (int q = 0; q < 4; q++) { accg[mi][ni][q] = 0.f; accu[mi][ni][q] = 0.f; }

    int nk = K >> 5;

    float4 sa[4], s1[2], s3[2];
#pragma unroll
    for (int j = 0; j < 4; j++) { sa[j] = *(const float4*)aptr[j]; aptr[j] += 32; }
#pragma unroll
    for (int j = 0; j < 2; j++) {
        s1[j] = *(const float4*)b1ptr[j]; b1ptr[j] += (size_t)32 * N;
        s3[j] = *(const float4*)b3ptr[j]; b3ptr[j] += (size_t)32 * N;
    }

    for (int kt = 0; kt < nk; kt++) {
#pragma unroll
        for (int j = 0; j < 4; j++) {
            int v = tid + j * 256;
            float* d = &As[v >> 3][(v & 7) * 4];
            d[0] = __uint_as_float(f2tf32(sa[j].x));
            d[1] = __uint_as_float(f2tf32(sa[j].y));
            d[2] = __uint_as_float(f2tf32(sa[j].z));
            d[3] = __uint_as_float(f2tf32(sa[j].w));
        }
#pragma unroll
        for (int j = 0; j < 2; j++) {
            int v = tid + j * 256;
            float* d1 = &B1s[v >> 4][(v & 15) * 4];
            d1[0] = __uint_as_float(f2tf32(s1[j].x));
            d1[1] = __uint_as_float(f2tf32(s1[j].y));
            d1[2] = __uint_as_float(f2tf32(s1[j].z));
            d1[3] = __uint_as_float(f2tf32(s1[j].w));
            float* d3 = &B3s[v >> 4][(v & 15) * 4];
            d3[0] = __uint_as_float(f2tf32(s3[j].x));
            d3[1] = __uint_as_float(f2tf32(s3[j].y));
            d3[2] = __uint_as_float(f2tf32(s3[j].z));
            d3[3] = __uint_as_float(f2tf32(s3[j].w));
        }
        __syncthreads();

        if (kt + 1 < nk) {
#pragma unroll
            for (int j = 0; j < 4; j++) { sa[j] = *(const float4*)aptr[j]; aptr[j] += 32; }
#pragma unroll
            for (int j = 0; j < 2; j++) {
                s1[j] = *(const float4*)b1ptr[j]; b1ptr[j] += (size_t)32 * N;
                s3[j] = *(const float4*)b3ptr[j]; b3ptr[j] += (size_t)32 * N;
            }
        }

#pragma unroll
        for (int ks = 0; ks < 4; ks++) {
            int k0 = ks * 8;
            uint32_t af[2][4];
#pragma unroll
            for (int mi = 0; mi < 2; mi++) {
                int r = wm + mi * 16 + (lane >> 2);
                int kc = k0 + (lane & 3);
                af[mi][0] = __float_as_uint(As[r][kc]);
                af[mi][1] = __float_as_uint(As[r + 8][kc]);
                af[mi][2] = __float_as_uint(As[r][kc + 4]);
                af[mi][3] = __float_as_uint(As[r + 8][kc + 4]);
            }
#pragma unroll
            for (int ni = 0; ni < 4; ni++) {
                int c = wn + ni * 8 + (lane >> 2);
                int kr = k0 + (lane & 3);
                uint32_t g0 = __float_as_uint(B1s[kr][c]);
                uint32_t g1 = __float_as_uint(B1s[kr + 4][c]);
                uint32_t u0 = __float_as_uint(B3s[kr][c]);
                uint32_t u1 = __float_as_uint(B3s[kr + 4][c]);
#pragma unroll
                for (int mi = 0; mi < 2; mi++) {
                    mma_tf32(accg[mi][ni], af[mi], g0, g1);
                    mma_tf32(accu[mi][ni], af[mi], u0, u1);
                }
            }
        }
        __syncthreads();
    }

    // epilogue: h = silu(g) * u, in registers; coalesced float2 stores
#pragma unroll
    for (int mi = 0; mi < 2; mi++) {
        int r0 = row0 + wm + mi * 16 + (lane >> 2);
        int r1 = r0 + 8;
#pragma unroll
        for (int ni = 0; ni < 4; ni++) {
            int c = col0 + wn + ni * 8 + (lane & 3) * 2;
            if (r0 < M) {
                float* p = C + (size_t)(base + r0) * N + c;
                p[0] = silu(accg[mi][ni][0]) * accu[mi][ni][0];
                p[1] = silu(accg[mi][ni][1]) * accu[mi][ni][1];
            }
            if (r1 < M) {
                float* p = C + (size_t)(base + r1) * N + c;
                p[0] = silu(accg[mi][ni][2]) * accu[mi][ni][2];
                p[1] = silu(accg[mi][ni][3]) * accu[mi][ni][3];
            }
        }
    }
}

// ---------------------------------------------------------------------------
// 4b) plain tf32 GEMM (R2-proven), 128x128 tile, for the down-projections
// ---------------------------------------------------------------------------
__global__ void __launch_bounds__(256, 1) sgemm_tc_kernel(
    const float* __restrict__ A, const float* __restrict__ B, float* __restrict__ C,
    int N, int K, long strideB, int Mfixed, int useCounts, int useGather)
{
    __shared__ float As[128][36];
    __shared__ float Bs[32][136];

    int e = blockIdx.z;
    int M, base;
    if (useCounts) { M = g_counts[e]; base = g_offsets[e]; }
    else           { M = Mfixed;      base = 0; }
    int row0 = blockIdx.y * 128;
    if (row0 >= M) return;
    int col0 = blockIdx.x * 128;
    const float* Bp = B + (size_t)e * strideB;

    int tid  = threadIdx.x;
    int lane = tid & 31;
    int wid  = tid >> 5;
    int wm   = (wid & 1) * 64;
    int wn   = (wid >> 1) * 32;

    const float* aptr[4];
#pragma unroll
    for (int j = 0; j < 4; j++) {
        int v = tid + j * 256;
        int r = v >> 3;
        int gr = row0 + r; if (gr > M - 1) gr = M - 1;
        long arow = useGather ? (long)g_slot_token[base + gr] : (long)(base + gr);
        aptr[j] = A + (size_t)arow * K + (v & 7) * 4;
    }
    const float* bptr[4];
#pragma unroll
    for (int j = 0; j < 4; j++) {
        int v = tid + j * 256;
        bptr[j] = Bp + (size_t)(v >> 5) * N + col0 + (v & 31) * 4;
    }

    float acc[4][4][4];
#pragma unroll
    for (int mi = 0; mi < 4; mi++)
#pragma unroll
        for (int ni = 0; ni < 4; ni++)
#pragma unroll
            for (int q = 0; q < 4; q++) acc[mi][ni][q] = 0.f;

    int nk = K >> 5;

    float4 sa[4], sb[4];
#pragma unroll
    for (int j = 0; j < 4; j++) { sa[j] = *(const float4*)aptr[j]; aptr[j] += 32; }
#pragma unroll
    for (int j = 0; j < 4; j++) { sb[j] = *(const float4*)bptr[j]; bptr[j] += (size_t)32 * N; }

    for (int kt = 0; kt < nk; kt++) {
#pragma unroll
        for (int j = 0; j < 4; j++) {
            int v = tid + j * 256;
            float* d = &As[v >> 3][(v & 7) * 4];
            d[0] = __uint_as_float(f2tf32(sa[j].x));
            d[1] = __uint_as_float(f2tf32(sa[j].y));
            d[2] = __uint_as_float(f2tf32(sa[j].z));
            d[3] = __uint_as_float(f2tf32(sa[j].w));
        }
#pragma unroll
        for (int j = 0; j < 4; j++) {
            int v = tid + j * 256;
            float* d = &Bs[v >> 5][(v & 31) * 4];
            d[0] = __uint_as_float(f2tf32(sb[j].x));
            d[1] = __uint_as_float(f2tf32(sb[j].y));
            d[2] = __uint_as_float(f2tf32(sb[j].z));
            d[3] = __uint_as_float(f2tf32(sb[j].w));
        }
        __syncthreads();

        if (kt + 1 < nk) {
#pragma unroll
            for (int j = 0; j < 4; j++) { sa[j] = *(const float4*)aptr[j]; aptr[j] += 32; }
#pragma unroll
            for (int j = 0; j < 4; j++) { sb[j] = *(const float4*)bptr[j]; bptr[j] += (size_t)32 * N; }
        }

#pragma unroll
        for (int ks = 0; ks < 4; ks++) {
            int k0 = ks * 8;
            uint32_t af[4][4];
#pragma unroll
            for (int mi = 0; mi < 4; mi++) {
                int r = wm + mi * 16 + (lane >> 2);
                int kc = k0 + (lane & 3);
                af[mi][0] = __float_as_uint(As[r][kc]);
                af[mi][1] = __float_as_uint(As[r + 8][kc]);
                af[mi][2] = __float_as_uint(As[r][kc + 4]);
                af[mi][3] = __float_as_uint(As[r + 8][kc + 4]);
            }
#pragma unroll
            for (int ni = 0; ni < 4; ni++) {
                int c = wn + ni * 8 + (lane >> 2);
                uint32_t b0 = __float_as_uint(Bs[k0 + (lane & 3)][c]);
                uint32_t b1 = __float_as_uint(Bs[k0 + 4 + (lane & 3)][c]);
#pragma unroll
                for (int mi = 0; mi < 4; mi++)
                    mma_tf32(acc[mi][ni], af[mi], b0, b1);
            }
        }
        __syncthreads();
    }

#pragma unroll
    for (int mi = 0; mi < 4; mi++) {
        int r0 = row0 + wm + mi * 16 + (lane >> 2);
        int r1 = r0 + 8;
#pragma unroll
        for (int ni = 0; ni < 4; ni++) {
            int c = col0 + wn + ni * 8 + (lane & 3) * 2;
            if (r0 < M) {
                float* p = C + (size_t)(base + r0) * N + c;
                p[0] = acc[mi][ni][0]; p[1] = acc[mi][ni][1];
            }
            if (r1 < M) {
                float* p = C + (size_t)(base + r1) * N + c;
                p[0] = acc[mi][ni][2]; p[1] = acc[mi][ni][3];
            }
        }
    }
}

// ---------------------------------------------------------------------------
// 6) combine: out[t] = w0*y[s0] + w1*y[s1] + sig[t]*ys[t]
// ---------------------------------------------------------------------------
__global__ void __launch_bounds__(128) combine_kernel(float* __restrict__ out)
{
    int t = blockIdx.x;
    int j = threadIdx.x;
    float w0 = g_topk_w[2 * t], w1 = g_topk_w[2 * t + 1];
    int   s0 = g_slot_of[2 * t], s1 = g_slot_of[2 * t + 1];
    float sg = g_sig[t];
    const float4* y4  = (const float4*)g_y;
    const float4* ys4 = (const float4*)g_ys;
    float4 a = y4[(size_t)s0 * 128 + j];
    float4 b = y4[(size_t)s1 * 128 + j];
    float4 c = ys4[(size_t)t * 128 + j];
    float4 r;
    r.x = w0 * a.x + w1 * b.x + sg * c.x;
    r.y = w0 * a.y + w1 * b.y + sg * c.y;
    r.z = w0 * a.z + w1 * b.z + sg * c.z;
    r.w = w0 * a.w + w1 * b.w + sg * c.w;
    ((float4*)out)[(size_t)t * 128 + j] = r;
}

// ---------------------------------------------------------------------------
// launch
// ---------------------------------------------------------------------------
extern "C" void kernel_launch(void* const* d_in, const int* in_sizes, int n_in,
                              void* d_out, int out_size)
{
    const float* x     = (const float*)d_in[0];
    const float* gate  = (const float*)d_in[1];
    const float* w1    = (const float*)d_in[2];
    const float* w2    = (const float*)d_in[3];
    const float* w3    = (const float*)d_in[4];
    const float* sw1   = (const float*)d_in[5];
    const float* sw2   = (const float*)d_in[6];
    const float* sw3   = (const float*)d_in[7];
    const float* sgate = (const float*)d_in[8];
    float* out = (float*)d_out;

    float* logits = nullptr;
    if ((size_t)out_size >= (size_t)T_TOK * HID + (size_t)T_TOK * NEXP)
        logits = out + (size_t)T_TOK * HID;

    float *bufA, *bufB, *ybuf, *ysbuf;
    cudaGetSymbolAddress((void**)&bufA,  g_bufA);
    cudaGetSymbolAddress((void**)&bufB,  g_bufB);
    cudaGetSymbolAddress((void**)&ybuf,  g_y);
    cudaGetSymbolAddress((void**)&ysbuf, g_ys);

    init_kernel<<<1, 32>>>();
    router_kernel<<<T_TOK / 8, 256>>>(x, gate, sgate, logits);
    prefix_kernel<<<1, 32>>>();
    scatter_kernel<<<T_TOK / 256, 256>>>();

    // MoE stage A fused: h = silu(X_g@w1[e]) * (X_g@w3[e]) -> bufA
    dual_swiglu_kernel<<<dim3(MOEI / 64, T_TOK / 128, NEXP), 256>>>(
        x, w1, w3, bufA, MOEI, HID, (long)HID * MOEI, 0, 1, 1);
    // MoE stage B: y_slot = h @ w2[e]
    sgemm_tc_kernel<<<dim3(HID / 128, T_TOK / 128, NEXP), 256>>>(
        bufA, w2, ybuf, HID, MOEI, (long)MOEI * HID, 0, 1, 0);

    // Shared expert fused stage A -> bufB
    dual_swiglu_kernel<<<dim3(SHI / 64, T_TOK / 128, 1), 256>>>(
        x, sw1, sw3, bufB, SHI, HID, 0L, T_TOK, 0, 0);
    // Shared stage B
    sgemm_tc_kernel<<<dim3(HID / 128, T_TOK / 128, 1), 256>>>(
        bufB, sw2, ysbuf, HID, SHI, 0L, T_TOK, 0, 0);

    combine_kernel<<<T_TOK, 128>>>(out);
}

// round 9
// speedup vs baseline: 1.2462x; 1.0199x over previous
#include <cuda_runtime.h>
#include <cuda_bf16.h>
#include <math.h>
#include <stdint.h>

// Problem constants
#define T_TOK 49152          // B*S*N = 2*24*1024
#define HID   512
#define NEXP  8
#define MOEI  1024
#define SHI   2048
#define NSLOT (2 * T_TOK)    // top-2 -> exactly 2 slots per token

// ---------------------------------------------------------------------------
// Scratch (static __device__ arrays; no allocation anywhere)
// ---------------------------------------------------------------------------
__device__ float g_bufA[100663296];             // h for MoE (2T x MOEI)
__device__ float g_bufB[100663296];             // h for shared (T x SHI)
__device__ float g_y  [(size_t)NSLOT * HID];    // per-slot expert output
__device__ int   g_topk_idx[NSLOT];
__device__ float g_topk_w [NSLOT];
__device__ float g_sig    [T_TOK];
__device__ int   g_counts [NEXP];
__device__ int   g_offsets[NEXP];
__device__ int   g_cursor [NEXP];
__device__ int   g_slot_token[NSLOT];           // slot -> token
__device__ int   g_slot_of   [NSLOT];           // (token,k) -> slot

// ---------------------------------------------------------------------------
// helpers
// ---------------------------------------------------------------------------
__device__ __forceinline__ uint32_t f2tf32(float x) {
    uint32_t r;
    asm("cvt.rna.tf32.f32 %0, %1;" : "=r"(r) : "f"(x));
    return r;
}

__device__ __forceinline__ void mma_tf32(float* c, const uint32_t* a,
                                         uint32_t b0, uint32_t b1) {
    asm volatile(
        "mma.sync.aligned.m16n8k8.row.col.f32.tf32.tf32.f32 "
        "{%0,%1,%2,%3},{%4,%5,%6,%7},{%8,%9},{%0,%1,%2,%3};"
        : "+f"(c[0]), "+f"(c[1]), "+f"(c[2]), "+f"(c[3])
        : "r"(a[0]), "r"(a[1]), "r"(a[2]), "r"(a[3]), "r"(b0), "r"(b1));
}

__device__ __forceinline__ float silu(float x) {
    return x * (1.f / (1.f + __expf(-x)));
}

// ---------------------------------------------------------------------------
// 0) zero counters
// ---------------------------------------------------------------------------
__global__ void init_kernel() {
    int i = threadIdx.x;
    if (i < NEXP) { g_counts[i] = 0; g_cursor[i] = 0; }
}

// ---------------------------------------------------------------------------
// 1) router
// ---------------------------------------------------------------------------
__global__ void __launch_bounds__(256) router_kernel(
    const float* __restrict__ x, const float* __restrict__ gw,
    const float* __restrict__ sg, float* __restrict__ logits_out)
{
    __shared__ float s_gw[HID * NEXP];
    __shared__ float s_sg[HID];
    for (int i = threadIdx.x; i < HID * NEXP; i += 256) s_gw[i] = gw[i];
    for (int i = threadIdx.x; i < HID; i += 256) s_sg[i] = sg[i];
    __syncthreads();

    int warp = threadIdx.x >> 5, lane = threadIdx.x & 31;
    int t = blockIdx.x * 8 + warp;
    const float* xr = x + (size_t)t * HID;

    float acc[NEXP];
#pragma unroll
    for (int e = 0; e < NEXP; e++) acc[e] = 0.f;
    float accs = 0.f;

#pragma unroll 4
    for (int i = 0; i < 16; i++) {
        int h = i * 32 + lane;
        float xv = xr[h];
#pragma unroll
        for (int e = 0; e < NEXP; e++) acc[e] += xv * s_gw[h * NEXP + e];
        accs += xv * s_sg[h];
    }
#pragma unroll
    for (int off = 16; off; off >>= 1) {
#pragma unroll
        for (int e = 0; e < NEXP; e++)
            acc[e] += __shfl_xor_sync(0xffffffff, acc[e], off);
        accs += __shfl_xor_sync(0xffffffff, accs, off);
    }

    if (lane == 0) {
        if (logits_out) {
#pragma unroll
            for (int e = 0; e < NEXP; e++) logits_out[(size_t)t * NEXP + e] = acc[e];
        }
        float m = acc[0];
#pragma unroll
        for (int e = 1; e < NEXP; e++) m = fmaxf(m, acc[e]);
        float p[NEXP], sum = 0.f;
#pragma unroll
        for (int e = 0; e < NEXP; e++) { p[e] = expf(acc[e] - m); sum += p[e]; }
        float inv = 1.f / sum;
#pragma unroll
        for (int e = 0; e < NEXP; e++) p[e] *= inv;

        int i1 = 0;
#pragma unroll
        for (int e = 1; e < NEXP; e++) if (p[e] > p[i1]) i1 = e;
        int i2 = (i1 == 0) ? 1 : 0;
#pragma unroll
        for (int e = 0; e < NEXP; e++) if (e != i1 && e != i2 && p[e] > p[i2]) i2 = e;

        g_topk_idx[2 * t]     = i1; g_topk_w[2 * t]     = p[i1];
        g_topk_idx[2 * t + 1] = i2; g_topk_w[2 * t + 1] = p[i2];
        atomicAdd(&g_counts[i1], 1);
        atomicAdd(&g_counts[i2], 1);
        g_sig[t] = 1.f / (1.f + expf(-accs));
    }
}

// ---------------------------------------------------------------------------
// 2) prefix, 3) scatter
// ---------------------------------------------------------------------------
__global__ void prefix_kernel() {
    if (threadIdx.x == 0) {
        int s = 0;
        for (int e = 0; e < NEXP; e++) { g_offsets[e] = s; g_cursor[e] = s; s += g_counts[e]; }
    }
}

__global__ void scatter_kernel() {
    int t = blockIdx.x * 256 + threadIdx.x;
    if (t >= T_TOK) return;
#pragma unroll
    for (int k = 0; k < 2; k++) {
        int e = g_topk_idx[2 * t + k];
        int pos = atomicAdd(&g_cursor[e], 1);
        g_slot_token[pos] = t;
        g_slot_of[2 * t + k] = pos;
    }
}

// ---------------------------------------------------------------------------
// 4a) dual tf32 GEMM + in-register SwiGLU, ping-pong smem.
//     C = silu(A@B1) * (A@B3).  Block 128x64, 8 warps 4(m)x2(n).
//     Dynamic smem: 2 buffers of (128*36 A + 2*32*72 B) floats.
// ---------------------------------------------------------------------------
#define DUAL_BUF (128 * 36 + 2 * 32 * 72)       // floats per buffer: 9216
#define DUAL_SMEM (2 * DUAL_BUF * 4)            // 73728 bytes

__global__ void __launch_bounds__(256, 1) dual_swiglu_kernel(
    const float* __restrict__ A, const float* __restrict__ B1,
    const float* __restrict__ B3, float* __restrict__ C,
    int N, int K, long strideB, int Mfixed, int useCounts, int useGather)
{
    extern __shared__ float sm[];

    int e = blockIdx.z;
    int M, base;
    if (useCounts) { M = g_counts[e]; base = g_offsets[e]; }
    else           { M = Mfixed;      base = 0; }
    int row0 = blockIdx.y * 128;
    if (row0 >= M) return;
    int col0 = blockIdx.x * 64;
    const float* B1p = B1 + (size_t)e * strideB;
    const float* B3p = B3 + (size_t)e * strideB;

    int tid  = threadIdx.x;
    int lane = tid & 31;
    int wid  = tid >> 5;
    int wm   = (wid >> 1) * 32;
    int wn   = (wid & 1) * 32;

    const float* aptr[4];
    int asto[4];
#pragma unroll
    for (int j = 0; j < 4; j++) {
        int v = tid + j * 256;
        int r = v >> 3;
        int gr = row0 + r; if (gr > M - 1) gr = M - 1;
        long arow = useGather ? (long)g_slot_token[base + gr] : (long)(base + gr);
        aptr[j] = A + (size_t)arow * K + (v & 7) * 4;
        asto[j] = r * 36 + (v & 7) * 4;
    }
    const float* b1ptr[2]; const float* b3ptr[2];
    int bsto[2];
#pragma unroll
    for (int j = 0; j < 2; j++) {
        int v = tid + j * 256;
        size_t off = (size_t)(v >> 4) * N + col0 + (v & 15) * 4;
        b1ptr[j] = B1p + off;
        b3ptr[j] = B3p + off;
        bsto[j] = (v >> 4) * 72 + (v & 15) * 4;
    }

    float accg[2][4][4], accu[2][4][4];
#pragma unroll
    for (int mi = 0; mi < 2; mi++)
#pragma unroll
        for (int ni = 0; ni < 4; ni++)
#pragma unroll
            for (int q = 0; q < 4; q++) { accg[mi][ni][q] = 0.f; accu[mi][ni][q] = 0.f; }

    int nk = K >> 5;

    float4 sa[4], s1[2], s3[2];
#pragma unroll
    for (int j = 0; j < 4; j++) { sa[j] = *(const float4*)aptr[j]; aptr[j] += 32; }
#pragma unroll
    for (int j = 0; j < 2; j++) {
        s1[j] = *(const float4*)b1ptr[j]; b1ptr[j] += (size_t)32 * N;
        s3[j] = *(const float4*)b3ptr[j]; b3ptr[j] += (size_t)32 * N;
    }
    // store tile 0 into buf 0
    {
        float* Ab = sm;
        float* B1b = sm + 128 * 36;
        float* B3b = B1b + 32 * 72;
#pragma unroll
        for (int j = 0; j < 4; j++) {
            float* d = Ab + asto[j];
            d[0] = __uint_as_float(f2tf32(sa[j].x));
            d[1] = __uint_as_float(f2tf32(sa[j].y));
            d[2] = __uint_as_float(f2tf32(sa[j].z));
            d[3] = __uint_as_float(f2tf32(sa[j].w));
        }
#pragma unroll
        for (int j = 0; j < 2; j++) {
            float* d1 = B1b + bsto[j];
            d1[0] = __uint_as_float(f2tf32(s1[j].x));
            d1[1] = __uint_as_float(f2tf32(s1[j].y));
            d1[2] = __uint_as_float(f2tf32(s1[j].z));
            d1[3] = __uint_as_float(f2tf32(s1[j].w));
            float* d3 = B3b + bsto[j];
            d3[0] = __uint_as_float(f2tf32(s3[j].x));
            d3[1] = __uint_as_float(f2tf32(s3[j].y));
            d3[2] = __uint_as_float(f2tf32(s3[j].z));
            d3[3] = __uint_as_float(f2tf32(s3[j].w));
        }
    }
    __syncthreads();

    for (int kt = 0; kt < nk; kt++) {
        int cur = kt & 1;
        float* Ab  = sm + cur * DUAL_BUF;
        float* B1b = Ab + 128 * 36;
        float* B3b = B1b + 32 * 72;

        if (kt + 1 < nk) {
#pragma unroll
            for (int j = 0; j < 4; j++) { sa[j] = *(const float4*)aptr[j]; aptr[j] += 32; }
#pragma unroll
            for (int j = 0; j < 2; j++) {
                s1[j] = *(const float4*)b1ptr[j]; b1ptr[j] += (size_t)32 * N;
                s3[j] = *(const float4*)b3ptr[j]; b3ptr[j] += (size_t)32 * N;
            }
        }

#pragma unroll
        for (int ks = 0; ks < 4; ks++) {
            int k0 = ks * 8;
            uint32_t af[2][4];
#pragma unroll
            for (int mi = 0; mi < 2; mi++) {
                int r = wm + mi * 16 + (lane >> 2);
                int kc = k0 + (lane & 3);
                af[mi][0] = __float_as_uint(Ab[r * 36 + kc]);
                af[mi][1] = __float_as_uint(Ab[(r + 8) * 36 + kc]);
                af[mi][2] = __float_as_uint(Ab[r * 36 + kc + 4]);
                af[mi][3] = __float_as_uint(Ab[(r + 8) * 36 + kc + 4]);
            }
#pragma unroll
            for (int ni = 0; ni < 4; ni++) {
                int c = wn + ni * 8 + (lane >> 2);
                int kr = k0 + (lane & 3);
                uint32_t g0 = __float_as_uint(B1b[kr * 72 + c]);
                uint32_t g1 = __float_as_uint(B1b[(kr + 4) * 72 + c]);
                uint32_t u0 = __float_as_uint(B3b[kr * 72 + c]);
                uint32_t u1 = __float_as_uint(B3b[(kr + 4) * 72 + c]);
#pragma unroll
                for (int mi = 0; mi < 2; mi++) {
                    mma_tf32(accg[mi][ni], af[mi], g0, g1);
                    mma_tf32(accu[mi][ni], af[mi], u0, u1);
                }
            }
        }

        if (kt + 1 < nk) {
            float* Ab2  = sm + (cur ^ 1) * DUAL_BUF;
            float* B1b2 = Ab2 + 128 * 36;
            float* B3b2 = B1b2 + 32 * 72;
#pragma unroll
            for (int j = 0; j < 4; j++) {
                float* d = Ab2 + asto[j];
                d[0] = __uint_as_float(f2tf32(sa[j].x));
                d[1] = __uint_as_float(f2tf32(sa[j].y));
                d[2] = __uint_as_float(f2tf32(sa[j].z));
                d[3] = __uint_as_float(f2tf32(sa[j].w));
            }
#pragma unroll
            for (int j = 0; j < 2; j++) {
                float* d1 = B1b2 + bsto[j];
                d1[0] = __uint_as_float(f2tf32(s1[j].x));
                d1[1] = __uint_as_float(f2tf32(s1[j].y));
                d1[2] = __uint_as_float(f2tf32(s1[j].z));
                d1[3] = __uint_as_float(f2tf32(s1[j].w));
                float* d3 = B3b2 + bsto[j];
                d3[0] = __uint_as_float(f2tf32(s3[j].x));
                d3[1] = __uint_as_float(f2tf32(s3[j].y));
                d3[2] = __uint_as_float(f2tf32(s3[j].z));
                d3[3] = __uint_as_float(f2tf32(s3[j].w));
            }
        }
        __syncthreads();
    }

    // epilogue: h = silu(g) * u
#pragma unroll
    for (int mi = 0; mi < 2; mi++) {
        int r0 = row0 + wm + mi * 16 + (lane >> 2);
        int r1 = r0 + 8;
#pragma unroll
        for (int ni = 0; ni < 4; ni++) {
            int c = col0 + wn + ni * 8 + (lane & 3) * 2;
            if (r0 < M) {
                float* p = C + (size_t)(base + r0) * N + c;
                p[0] = silu(accg[mi][ni][0]) * accu[mi][ni][0];
                p[1] = silu(accg[mi][ni][1]) * accu[mi][ni][1];
            }
            if (r1 < M) {
                float* p = C + (size_t)(base + r1) * N + c;
                p[0] = silu(accg[mi][ni][2]) * accu[mi][ni][2];
                p[1] = silu(accg[mi][ni][3]) * accu[mi][ni][3];
            }
        }
    }
}

// ---------------------------------------------------------------------------
// 4b) plain tf32 GEMM, 128x128 tile, ping-pong smem.
//     fuseCombine: epilogue writes out = w0*y[s0] + w1*y[s1] + sig*acc
//     (rows are tokens; requires base=0, N=HID).
// ---------------------------------------------------------------------------
#define SG_BUF (128 * 36 + 32 * 136)            // floats per buffer: 8960
#define SG_SMEM (2 * SG_BUF * 4)                // 71680 bytes

__global__ void __launch_bounds__(256, 1) sgemm_tc_kernel(
    const float* __restrict__ A, const float* __restrict__ B, float* __restrict__ C,
    int N, int K, long strideB, int Mfixed, int useCounts, int useGather,
    int fuseCombine)
{
    extern __shared__ float sm[];

    int e = blockIdx.z;
    int M, base;
    if (useCounts) { M = g_counts[e]; base = g_offsets[e]; }
    else           { M = Mfixed;      base = 0; }
    int row0 = blockIdx.y * 128;
    if (row0 >= M) return;
    int col0 = blockIdx.x * 128;
    const float* Bp = B + (size_t)e * strideB;

    int tid  = threadIdx.x;
    int lane = tid & 31;
    int wid  = tid >> 5;
    int wm   = (wid & 1) * 64;
    int wn   = (wid >> 1) * 32;

    const float* aptr[4];
    int asto[4];
#pragma unroll
    for (int j = 0; j < 4; j++) {
        int v = tid + j * 256;
        int r = v >> 3;
        int gr = row0 + r; if (gr > M - 1) gr = M - 1;
        long arow = useGather ? (long)g_slot_token[base + gr] : (long)(base + gr);
        aptr[j] = A + (size_t)arow * K + (v & 7) * 4;
        asto[j] = r * 36 + (v & 7) * 4;
    }
    const float* bptr[4];
    int bsto[4];
#pragma unroll
    for (int j = 0; j < 4; j++) {
        int v = tid + j * 256;
        bptr[j] = Bp + (size_t)(v >> 5) * N + col0 + (v & 31) * 4;
        bsto[j] = (v >> 5) * 136 + (v & 31) * 4;
    }

    float acc[4][4][4];
#pragma unroll
    for (int mi = 0; mi < 4; mi++)
#pragma unroll
        for (int ni = 0; ni < 4; ni++)
#pragma unroll
            for (int q = 0; q < 4; q++) acc[mi][ni][q] = 0.f;

    int nk = K >> 5;

    float4 sa[4], sb[4];
#pragma unroll
    for (int j = 0; j < 4; j++) { sa[j] = *(const float4*)aptr[j]; aptr[j] += 32; }
#pragma unroll
    for (int j = 0; j < 4; j++) { sb[j] = *(const float4*)bptr[j]; bptr[j] += (size_t)32 * N; }
    {
        float* Ab = sm;
        float* Bb = sm + 128 * 36;
#pragma unroll
        for (int j = 0; j < 4; j++) {
            float* d = Ab + asto[j];
            d[0] = __uint_as_float(f2tf32(sa[j].x));
            d[1] = __uint_as_float(f2tf32(sa[j].y));
            d[2] = __uint_as_float(f2tf32(sa[j].z));
            d[3] = __uint_as_float(f2tf32(sa[j].w));
        }
#pragma unroll
        for (int j = 0; j < 4; j++) {
            float* d = Bb + bsto[j];
            d[0] = __uint_as_float(f2tf32(sb[j].x));
            d[1] = __uint_as_float(f2tf32(sb[j].y));
            d[2] = __uint_as_float(f2tf32(sb[j].z));
            d[3] = __uint_as_float(f2tf32(sb[j].w));
        }
    }
    __syncthreads();

    for (int kt = 0; kt < nk; kt++) {
        int cur = kt & 1;
        float* Ab = sm + cur * SG_BUF;
        float* Bb = Ab + 128 * 36;

        if (kt + 1 < nk) {
#pragma unroll
            for (int j = 0; j < 4; j++) { sa[j] = *(const float4*)aptr[j]; aptr[j] += 32; }
#pragma unroll
            for (int j = 0; j < 4; j++) { sb[j] = *(const float4*)bptr[j]; bptr[j] += (size_t)32 * N; }
        }

#pragma unroll
        for (int ks = 0; ks < 4; ks++) {
            int k0 = ks * 8;
            uint32_t af[4][4];
#pragma unroll
            for (int mi = 0; mi < 4; mi++) {
                int r = wm + mi * 16 + (lane >> 2);
                int kc = k0 + (lane & 3);
                af[mi][0] = __float_as_uint(Ab[r * 36 + kc]);
                af[mi][1] = __float_as_uint(Ab[(r + 8) * 36 + kc]);
                af[mi][2] = __float_as_uint(Ab[r * 36 + kc + 4]);
                af[mi][3] = __float_as_uint(Ab[(r + 8) * 36 + kc + 4]);
            }
#pragma unroll
            for (int ni = 0; ni < 4; ni++) {
                int c = wn + ni * 8 + (lane >> 2);
                int kr = k0 + (lane & 3);
                uint32_t b0 = __float_as_uint(Bb[kr * 136 + c]);
                uint32_t b1 = __float_as_uint(Bb[(kr + 4) * 136 + c]);
#pragma unroll
                for (int mi = 0; mi < 4; mi++)
                    mma_tf32(acc[mi][ni], af[mi], b0, b1);
            }
        }

        if (kt + 1 < nk) {
            float* Ab2 = sm + (cur ^ 1) * SG_BUF;
            float* Bb2 = Ab2 + 128 * 36;
#pragma unroll
            for (int j = 0; j < 4; j++) {
                float* d = Ab2 + asto[j];
                d[0] = __uint_as_float(f2tf32(sa[j].x));
                d[1] = __uint_as_float(f2tf32(sa[j].y));
                d[2] = __uint_as_float(f2tf32(sa[j].z));
                d[3] = __uint_as_float(f2tf32(sa[j].w));
            }
#pragma unroll
            for (int j = 0; j < 4; j++) {
                float* d = Bb2 + bsto[j];
                d[0] = __uint_as_float(f2tf32(sb[j].x));
                d[1] = __uint_as_float(f2tf32(sb[j].y));
                d[2] = __uint_as_float(f2tf32(sb[j].z));
                d[3] = __uint_as_float(f2tf32(sb[j].w));
            }
        }
        __syncthreads();
    }

    // epilogue
#pragma unroll
    for (int mi = 0; mi < 4; mi++) {
        int r0 = row0 + wm + mi * 16 + (lane >> 2);
        int r1 = r0 + 8;
#pragma unroll
        for (int ni = 0; ni < 4; ni++) {
            int c = col0 + wn + ni * 8 + (lane & 3) * 2;
            if (!fuseCombine) {
                if (r0 < M) {
                    float* p = C + (size_t)(base + r0) * N + c;
                    p[0] = acc[mi][ni][0]; p[1] = acc[mi][ni][1];
                }
                if (r1 < M) {
                    float* p = C + (size_t)(base + r1) * N + c;
                    p[0] = acc[mi][ni][2]; p[1] = acc[mi][ni][3];
                }
            } else {
                if (r0 < M) {
                    int t = r0;
                    float w0 = g_topk_w[2 * t], w1 = g_topk_w[2 * t + 1];
                    int   s0 = g_slot_of[2 * t], s1 = g_slot_of[2 * t + 1];
                    float sg = g_sig[t];
                    float2 y0 = *(const float2*)&g_y[(size_t)s0 * HID + c];
                    float2 y1 = *(const float2*)&g_y[(size_t)s1 * HID + c];
                    float* p = C + (size_t)t * N + c;
                    p[0] = w0 * y0.x + w1 * y1.x + sg * acc[mi][ni][0];
                    p[1] = w0 * y0.y + w1 * y1.y + sg * acc[mi][ni][1];
                }
                if (r1 < M) {
                    int t = r1;
                    float w0 = g_topk_w[2 * t], w1 = g_topk_w[2 * t + 1];
                    int   s0 = g_slot_of[2 * t], s1 = g_slot_of[2 * t + 1];
                    float sg = g_sig[t];
                    float2 y0 = *(const float2*)&g_y[(size_t)s0 * HID + c];
                    float2 y1 = *(const float2*)&g_y[(size_t)s1 * HID + c];
                    float* p = C + (size_t)t * N + c;
                    p[0] = w0 * y0.x + w1 * y1.x + sg * acc[mi][ni][2];
                    p[1] = w0 * y0.y + w1 * y1.y + sg * acc[mi][ni][3];
                }
            }
        }
    }
}

// ---------------------------------------------------------------------------
// launch
// ---------------------------------------------------------------------------
extern "C" void kernel_launch(void* const* d_in, const int* in_sizes, int n_in,
                              void* d_out, int out_size)
{
    const float* x     = (const float*)d_in[0];
    const float* gate  = (const float*)d_in[1];
    const float* w1    = (const float*)d_in[2];
    const float* w2    = (const float*)d_in[3];
    const float* w3    = (const float*)d_in[4];
    const float* sw1   = (const float*)d_in[5];
    const float* sw2   = (const float*)d_in[6];
    const float* sw3   = (const float*)d_in[7];
    const float* sgate = (const float*)d_in[8];
    float* out = (float*)d_out;

    float* logits = nullptr;
    if ((size_t)out_size >= (size_t)T_TOK * HID + (size_t)T_TOK * NEXP)
        logits = out + (size_t)T_TOK * HID;

    float *bufA, *bufB, *ybuf;
    cudaGetSymbolAddress((void**)&bufA, g_bufA);
    cudaGetSymbolAddress((void**)&bufB, g_bufB);
    cudaGetSymbolAddress((void**)&ybuf, g_y);

    static int smem_set = 0;
    if (!smem_set) {
        cudaFuncSetAttribute(dual_swiglu_kernel,
                             cudaFuncAttributeMaxDynamicSharedMemorySize, DUAL_SMEM);
        cudaFuncSetAttribute(sgemm_tc_kernel,
                             cudaFuncAttributeMaxDynamicSharedMemorySize, SG_SMEM);
        smem_set = 1;
    }

    init_kernel<<<1, 32>>>();
    router_kernel<<<T_TOK / 8, 256>>>(x, gate, sgate, logits);
    prefix_kernel<<<1, 32>>>();
    scatter_kernel<<<T_TOK / 256, 256>>>();

    // MoE stage A fused: h = silu(X_g@w1[e]) * (X_g@w3[e]) -> bufA
    dual_swiglu_kernel<<<dim3(MOEI / 64, T_TOK / 128, NEXP), 256, DUAL_SMEM>>>(
        x, w1, w3, bufA, MOEI, HID, (long)HID * MOEI, 0, 1, 1);
    // MoE stage B: y_slot = h @ w2[e]
    sgemm_tc_kernel<<<dim3(HID / 128, T_TOK / 128, NEXP), 256, SG_SMEM>>>(
        bufA, w2, ybuf, HID, MOEI, (long)MOEI * HID, 0, 1, 0, 0);

    // Shared expert fused stage A -> bufB
    dual_swiglu_kernel<<<dim3(SHI / 64, T_TOK / 128, 1), 256, DUAL_SMEM>>>(
        x, sw1, sw3, bufB, SHI, HID, 0L, T_TOK, 0, 0);
    // Shared stage B with fused final combine -> out
    sgemm_tc_kernel<<<dim3(HID / 128, T_TOK / 128, 1), 256, SG_SMEM>>>(
        bufB, sw2, out, HID, SHI, 0L, T_TOK, 0, 0, 1);
}

// round 10
// speedup vs baseline: 1.3059x; 1.0479x over previous
#include <cuda_runtime.h>
#include <cuda_bf16.h>
#include <math.h>
#include <stdint.h>

// Problem constants
#define T_TOK 49152          // B*S*N = 2*24*1024
#define HID   512
#define NEXP  8
#define MOEI  1024
#define SHI   2048
#define NSLOT (2 * T_TOK)    // top-2 -> exactly 2 slots per token

// ---------------------------------------------------------------------------
// Scratch (static __device__ arrays; no allocation anywhere)
// ---------------------------------------------------------------------------
__device__ float g_bufA[100663296];             // h for MoE (2T x MOEI)
__device__ float g_bufB[100663296];             // h for shared (T x SHI)
__device__ float g_y  [(size_t)NSLOT * HID];    // per-slot expert output
__device__ int   g_topk_idx[NSLOT];
__device__ float g_topk_w [NSLOT];
__device__ float g_sig    [T_TOK];
__device__ int   g_counts [NEXP];
__device__ int   g_offsets[NEXP];
__device__ int   g_cursor [NEXP];
__device__ int   g_slot_token[NSLOT];           // slot -> token
__device__ int   g_slot_of   [NSLOT];           // (token,k) -> slot

// ---------------------------------------------------------------------------
// helpers
// ---------------------------------------------------------------------------
__device__ __forceinline__ uint32_t f2tf32(float x) {
    uint32_t r;
    asm("cvt.rna.tf32.f32 %0, %1;" : "=r"(r) : "f"(x));
    return r;
}

__device__ __forceinline__ void mma_tf32(float* c, const uint32_t* a,
                                         uint32_t b0, uint32_t b1) {
    asm volatile(
        "mma.sync.aligned.m16n8k8.row.col.f32.tf32.tf32.f32 "
        "{%0,%1,%2,%3},{%4,%5,%6,%7},{%8,%9},{%0,%1,%2,%3};"
        : "+f"(c[0]), "+f"(c[1]), "+f"(c[2]), "+f"(c[3])
        : "r"(a[0]), "r"(a[1]), "r"(a[2]), "r"(a[3]), "r"(b0), "r"(b1));
}

__device__ __forceinline__ float silu(float x) {
    return x * (1.f / (1.f + __expf(-x)));
}

// ---------------------------------------------------------------------------
// 0) zero counters
// ---------------------------------------------------------------------------
__global__ void init_kernel() {
    int i = threadIdx.x;
    if (i < NEXP) { g_counts[i] = 0; g_cursor[i] = 0; }
}

// ---------------------------------------------------------------------------
// 1) router
// ---------------------------------------------------------------------------
__global__ void __launch_bounds__(256) router_kernel(
    const float* __restrict__ x, const float* __restrict__ gw,
    const float* __restrict__ sg, float* __restrict__ logits_out)
{
    __shared__ float s_gw[HID * NEXP];
    __shared__ float s_sg[HID];
    for (int i = threadIdx.x; i < HID * NEXP; i += 256) s_gw[i] = gw[i];
    for (int i = threadIdx.x; i < HID; i += 256) s_sg[i] = sg[i];
    __syncthreads();

    int warp = threadIdx.x >> 5, lane = threadIdx.x & 31;
    int t = blockIdx.x * 8 + warp;
    const float* xr = x + (size_t)t * HID;

    float acc[NEXP];
#pragma unroll
    for (int e = 0; e < NEXP; e++) acc[e] = 0.f;
    float accs = 0.f;

#pragma unroll 4
    for (int i = 0; i < 16; i++) {
        int h = i * 32 + lane;
        float xv = xr[h];
#pragma unroll
        for (int e = 0; e < NEXP; e++) acc[e] += xv * s_gw[h * NEXP + e];
        accs += xv * s_sg[h];
    }
#pragma unroll
    for (int off = 16; off; off >>= 1) {
#pragma unroll
        for (int e = 0; e < NEXP; e++)
            acc[e] += __shfl_xor_sync(0xffffffff, acc[e], off);
        accs += __shfl_xor_sync(0xffffffff, accs, off);
    }

    if (lane == 0) {
        if (logits_out) {
#pragma unroll
            for (int e = 0; e < NEXP; e++) logits_out[(size_t)t * NEXP + e] = acc[e];
        }
        float m = acc[0];
#pragma unroll
        for (int e = 1; e < NEXP; e++) m = fmaxf(m, acc[e]);
        float p[NEXP], sum = 0.f;
#pragma unroll
        for (int e = 0; e < NEXP; e++) { p[e] = expf(acc[e] - m); sum += p[e]; }
        float inv = 1.f / sum;
#pragma unroll
        for (int e = 0; e < NEXP; e++) p[e] *= inv;

        int i1 = 0;
#pragma unroll
        for (int e = 1; e < NEXP; e++) if (p[e] > p[i1]) i1 = e;
        int i2 = (i1 == 0) ? 1 : 0;
#pragma unroll
        for (int e = 0; e < NEXP; e++) if (e != i1 && e != i2 && p[e] > p[i2]) i2 = e;

        g_topk_idx[2 * t]     = i1; g_topk_w[2 * t]     = p[i1];
        g_topk_idx[2 * t + 1] = i2; g_topk_w[2 * t + 1] = p[i2];
        atomicAdd(&g_counts[i1], 1);
        atomicAdd(&g_counts[i2], 1);
        g_sig[t] = 1.f / (1.f + expf(-accs));
    }
}

// ---------------------------------------------------------------------------
// 2) prefix, 3) scatter
// ---------------------------------------------------------------------------
__global__ void prefix_kernel() {
    if (threadIdx.x == 0) {
        int s = 0;
        for (int e = 0; e < NEXP; e++) { g_offsets[e] = s; g_cursor[e] = s; s += g_counts[e]; }
    }
}

__global__ void scatter_kernel() {
    int t = blockIdx.x * 256 + threadIdx.x;
    if (t >= T_TOK) return;
#pragma unroll
    for (int k = 0; k < 2; k++) {
        int e = g_topk_idx[2 * t + k];
        int pos = atomicAdd(&g_cursor[e], 1);
        g_slot_token[pos] = t;
        g_slot_of[2 * t + k] = pos;
    }
}

// ---------------------------------------------------------------------------
// 4a) dual tf32 GEMM + in-register SwiGLU, ping-pong smem.
//     MERGED launch: z=0..7 MoE experts (gathered, bufA), z=8..9 the two
//     column-halves of the shared expert (dense, bufB).
//     Block 128x64, 8 warps 4(m)x2(n). K=HID=512 for all.
// ---------------------------------------------------------------------------
#define DUAL_BUF (128 * 36 + 2 * 32 * 72)       // floats per buffer: 9216
#define DUAL_SMEM (2 * DUAL_BUF * 4)            // 73728 bytes

__global__ void __launch_bounds__(256, 2) dual_swiglu_kernel(
    const float* __restrict__ A,
    const float* __restrict__ W1m, const float* __restrict__ W3m, float* __restrict__ Cm,
    const float* __restrict__ W1s, const float* __restrict__ W3s, float* __restrict__ Cs)
{
    extern __shared__ float sm[];

    const int K = HID;
    int z = blockIdx.z;
    int M, base, N, col0, useGather;
    const float *B1p, *B3p;
    float* C;
    if (z < NEXP) {
        M = g_counts[z]; base = g_offsets[z]; useGather = 1;
        N = MOEI; col0 = blockIdx.x * 64;
        B1p = W1m + (size_t)z * HID * MOEI;
        B3p = W3m + (size_t)z * HID * MOEI;
        C = Cm;
    } else {
        M = T_TOK; base = 0; useGather = 0;
        N = SHI; col0 = (blockIdx.x + (z - NEXP) * 16) * 64;
        B1p = W1s; B3p = W3s;
        C = Cs;
    }
    int row0 = blockIdx.y * 128;
    if (row0 >= M) return;

    int tid  = threadIdx.x;
    int lane = tid & 31;
    int wid  = tid >> 5;
    int wm   = (wid >> 1) * 32;
    int wn   = (wid & 1) * 32;

    const float* aptr[4];
    int asto[4];
#pragma unroll
    for (int j = 0; j < 4; j++) {
        int v = tid + j * 256;
        int r = v >> 3;
        int gr = row0 + r; if (gr > M - 1) gr = M - 1;
        long arow = useGather ? (long)g_slot_token[base + gr] : (long)(base + gr);
        aptr[j] = A + (size_t)arow * K + (v & 7) * 4;
        asto[j] = r * 36 + (v & 7) * 4;
    }
    const float* b1ptr[2]; const float* b3ptr[2];
    int bsto[2];
#pragma unroll
    for (int j = 0; j < 2; j++) {
        int v = tid + j * 256;
        size_t off = (size_t)(v >> 4) * N + col0 + (v & 15) * 4;
        b1ptr[j] = B1p + off;
        b3ptr[j] = B3p + off;
        bsto[j] = (v >> 4) * 72 + (v & 15) * 4;
    }

    float accg[2][4][4], accu[2][4][4];
#pragma unroll
    for (int mi = 0; mi < 2; mi++)
#pragma unroll
        for (int ni = 0; ni < 4; ni++)
#pragma unroll
            for (int q = 0; q < 4; q++) { accg[mi][ni][q] = 0.f; accu[mi][ni][q] = 0.f; }

    int nk = K >> 5;

    float4 sa[4], s1[2], s3[2];
#pragma unroll
    for (int j = 0; j < 4; j++) { sa[j] = *(const float4*)aptr[j]; aptr[j] += 32; }
#pragma unroll
    for (int j = 0; j < 2; j++) {
        s1[j] = *(const float4*)b1ptr[j]; b1ptr[j] += (size_t)32 * N;
        s3[j] = *(const float4*)b3ptr[j]; b3ptr[j] += (size_t)32 * N;
    }
    {
        float* Ab = sm;
        float* B1b = sm + 128 * 36;
        float* B3b = B1b + 32 * 72;
#pragma unroll
        for (int j = 0; j < 4; j++) {
            float* d = Ab + asto[j];
            d[0] = __uint_as_float(f2tf32(sa[j].x));
            d[1] = __uint_as_float(f2tf32(sa[j].y));
            d[2] = __uint_as_float(f2tf32(sa[j].z));
            d[3] = __uint_as_float(f2tf32(sa[j].w));
        }
#pragma unroll
        for (int j = 0; j < 2; j++) {
            float* d1 = B1b + bsto[j];
            d1[0] = __uint_as_float(f2tf32(s1[j].x));
            d1[1] = __uint_as_float(f2tf32(s1[j].y));
            d1[2] = __uint_as_float(f2tf32(s1[j].z));
            d1[3] = __uint_as_float(f2tf32(s1[j].w));
            float* d3 = B3b + bsto[j];
            d3[0] = __uint_as_float(f2tf32(s3[j].x));
            d3[1] = __uint_as_float(f2tf32(s3[j].y));
            d3[2] = __uint_as_float(f2tf32(s3[j].z));
            d3[3] = __uint_as_float(f2tf32(s3[j].w));
        }
    }
    __syncthreads();

    for (int kt = 0; kt < nk; kt++) {
        int cur = kt & 1;
        float* Ab  = sm + cur * DUAL_BUF;
        float* B1b = Ab + 128 * 36;
        float* B3b = B1b + 32 * 72;

        if (kt + 1 < nk) {
#pragma unroll
            for (int j = 0; j < 4; j++) { sa[j] = *(const float4*)aptr[j]; aptr[j] += 32; }
#pragma unroll
            for (int j = 0; j < 2; j++) {
                s1[j] = *(const float4*)b1ptr[j]; b1ptr[j] += (size_t)32 * N;
                s3[j] = *(const float4*)b3ptr[j]; b3ptr[j] += (size_t)32 * N;
            }
        }

#pragma unroll
        for (int ks = 0; ks < 4; ks++) {
            int k0 = ks * 8;
            uint32_t af[2][4];
#pragma unroll
            for (int mi = 0; mi < 2; mi++) {
                int r = wm + mi * 16 + (lane >> 2);
                int kc = k0 + (lane & 3);
                af[mi][0] = __float_as_uint(Ab[r * 36 + kc]);
                af[mi][1] = __float_as_uint(Ab[(r + 8) * 36 + kc]);
                af[mi][2] = __float_as_uint(Ab[r * 36 + kc + 4]);
                af[mi][3] = __float_as_uint(Ab[(r + 8) * 36 + kc + 4]);
            }
#pragma unroll
            for (int ni = 0; ni < 4; ni++) {
                int c = wn + ni * 8 + (lane >> 2);
                int kr = k0 + (lane & 3);
                uint32_t g0 = __float_as_uint(B1b[kr * 72 + c]);
                uint32_t g1 = __float_as_uint(B1b[(kr + 4) * 72 + c]);
                uint32_t u0 = __float_as_uint(B3b[kr * 72 + c]);
                uint32_t u1 = __float_as_uint(B3b[(kr + 4) * 72 + c]);
#pragma unroll
                for (int mi = 0; mi < 2; mi++) {
                    mma_tf32(accg[mi][ni], af[mi], g0, g1);
                    mma_tf32(accu[mi][ni], af[mi], u0, u1);
                }
            }
        }

        if (kt + 1 < nk) {
            float* Ab2  = sm + (cur ^ 1) * DUAL_BUF;
            float* B1b2 = Ab2 + 128 * 36;
            float* B3b2 = B1b2 + 32 * 72;
#pragma unroll
            for (int j = 0; j < 4; j++) {
                float* d = Ab2 + asto[j];
                d[0] = __uint_as_float(f2tf32(sa[j].x));
                d[1] = __uint_as_float(f2tf32(sa[j].y));
                d[2] = __uint_as_float(f2tf32(sa[j].z));
                d[3] = __uint_as_float(f2tf32(sa[j].w));
            }
#pragma unroll
            for (int j = 0; j < 2; j++) {
                float* d1 = B1b2 + bsto[j];
                d1[0] = __uint_as_float(f2tf32(s1[j].x));
                d1[1] = __uint_as_float(f2tf32(s1[j].y));
                d1[2] = __uint_as_float(f2tf32(s1[j].z));
                d1[3] = __uint_as_float(f2tf32(s1[j].w));
                float* d3 = B3b2 + bsto[j];
                d3[0] = __uint_as_float(f2tf32(s3[j].x));
                d3[1] = __uint_as_float(f2tf32(s3[j].y));
                d3[2] = __uint_as_float(f2tf32(s3[j].z));
                d3[3] = __uint_as_float(f2tf32(s3[j].w));
            }
        }
        __syncthreads();
    }

    // epilogue: h = silu(g) * u
#pragma unroll
    for (int mi = 0; mi < 2; mi++) {
        int r0 = row0 + wm + mi * 16 + (lane >> 2);
        int r1 = r0 + 8;
#pragma unroll
        for (int ni = 0; ni < 4; ni++) {
            int c = col0 + wn + ni * 8 + (lane & 3) * 2;
            if (r0 < M) {
                float* p = C + (size_t)(base + r0) * N + c;
                p[0] = silu(accg[mi][ni][0]) * accu[mi][ni][0];
                p[1] = silu(accg[mi][ni][1]) * accu[mi][ni][1];
            }
            if (r1 < M) {
                float* p = C + (size_t)(base + r1) * N + c;
                p[0] = silu(accg[mi][ni][2]) * accu[mi][ni][2];
                p[1] = silu(accg[mi][ni][3]) * accu[mi][ni][3];
            }
        }
    }
}

// ---------------------------------------------------------------------------
// 4b) plain tf32 GEMM, 128x128 tile, ping-pong smem.
//     fuseCombine: epilogue writes out = w0*y[s0] + w1*y[s1] + sig*acc
// ---------------------------------------------------------------------------
#define SG_BUF (128 * 36 + 32 * 136)            // floats per buffer: 8960
#define SG_SMEM (2 * SG_BUF * 4)                // 71680 bytes

__global__ void __launch_bounds__(256, 2) sgemm_tc_kernel(
    const float* __restrict__ A, const float* __restrict__ B, float* __restrict__ C,
    int N, int K, long strideB, int Mfixed, int useCounts, int useGather,
    int fuseCombine)
{
    extern __shared__ float sm[];

    int e = blockIdx.z;
    int M, base;
    if (useCounts) { M = g_counts[e]; base = g_offsets[e]; }
    else           { M = Mfixed;      base = 0; }
    int row0 = blockIdx.y * 128;
    if (row0 >= M) return;
    int col0 = blockIdx.x * 128;
    const float* Bp = B + (size_t)e * strideB;

    int tid  = threadIdx.x;
    int lane = tid & 31;
    int wid  = tid >> 5;
    int wm   = (wid & 1) * 64;
    int wn   = (wid >> 1) * 32;

    const float* aptr[4];
    int asto[4];
#pragma unroll
    for (int j = 0; j < 4; j++) {
        int v = tid + j * 256;
        int r = v >> 3;
        int gr = row0 + r; if (gr > M - 1) gr = M - 1;
        long arow = useGather ? (long)g_slot_token[base + gr] : (long)(base + gr);
        aptr[j] = A + (size_t)arow * K + (v & 7) * 4;
        asto[j] = r * 36 + (v & 7) * 4;
    }
    const float* bptr[4];
    int bsto[4];
#pragma unroll
    for (int j = 0; j < 4; j++) {
        int v = tid + j * 256;
        bptr[j] = Bp + (size_t)(v >> 5) * N + col0 + (v & 31) * 4;
        bsto[j] = (v >> 5) * 136 + (v & 31) * 4;
    }

    float acc[4][4][4];
#pragma unroll
    for (int mi = 0; mi < 4; mi++)
#pragma unroll
        for (int ni = 0; ni < 4; ni++)
#pragma unroll
            for (int q = 0; q < 4; q++) acc[mi][ni][q] = 0.f;

    int nk = K >> 5;

    float4 sa[4], sb[4];
#pragma unroll
    for (int j = 0; j < 4; j++) { sa[j] = *(const float4*)aptr[j]; aptr[j] += 32; }
#pragma unroll
    for (int j = 0; j < 4; j++) { sb[j] = *(const float4*)bptr[j]; bptr[j] += (size_t)32 * N; }
    {
        float* Ab = sm;
        float* Bb = sm + 128 * 36;
#pragma unroll
        for (int j = 0; j < 4; j++) {
            float* d = Ab + asto[j];
            d[0] = __uint_as_float(f2tf32(sa[j].x));
            d[1] = __uint_as_float(f2tf32(sa[j].y));
            d[2] = __uint_as_float(f2tf32(sa[j].z));
            d[3] = __uint_as_float(f2tf32(sa[j].w));
        }
#pragma unroll
        for (int j = 0; j < 4; j++) {
            float* d = Bb + bsto[j];
            d[0] = __uint_as_float(f2tf32(sb[j].x));
            d[1] = __uint_as_float(f2tf32(sb[j].y));
            d[2] = __uint_as_float(f2tf32(sb[j].z));
            d[3] = __uint_as_float(f2tf32(sb[j].w));
        }
    }
    __syncthreads();

    for (int kt = 0; kt < nk; kt++) {
        int cur = kt & 1;
        float* Ab = sm + cur * SG_BUF;
        float* Bb = Ab + 128 * 36;

        if (kt + 1 < nk) {
#pragma unroll
            for (int j = 0; j < 4; j++) { sa[j] = *(const float4*)aptr[j]; aptr[j] += 32; }
#pragma unroll
            for (int j = 0; j < 4; j++) { sb[j] = *(const float4*)bptr[j]; bptr[j] += (size_t)32 * N; }
        }

#pragma unroll
        for (int ks = 0; ks < 4; ks++) {
            int k0 = ks * 8;
            uint32_t af[4][4];
#pragma unroll
            for (int mi = 0; mi < 4; mi++) {
                int r = wm + mi * 16 + (lane >> 2);
                int kc = k0 + (lane & 3);
                af[mi][0] = __float_as_uint(Ab[r * 36 + kc]);
                af[mi][1] = __float_as_uint(Ab[(r + 8) * 36 + kc]);
                af[mi][2] = __float_as_uint(Ab[r * 36 + kc + 4]);
                af[mi][3] = __float_as_uint(Ab[(r + 8) * 36 + kc + 4]);
            }
#pragma unroll
            for (int ni = 0; ni < 4; ni++) {
                int c = wn + ni * 8 + (lane >> 2);
                int kr = k0 + (lane & 3);
                uint32_t b0 = __float_as_uint(Bb[kr * 136 + c]);
                uint32_t b1 = __float_as_uint(Bb[(kr + 4) * 136 + c]);
#pragma unroll
                for (int mi = 0; mi < 4; mi++)
                    mma_tf32(acc[mi][ni], af[mi], b0, b1);
            }
        }

        if (kt + 1 < nk) {
            float* Ab2 = sm + (cur ^ 1) * SG_BUF;
            float* Bb2 = Ab2 + 128 * 36;
#pragma unroll
            for (int j = 0; j < 4; j++) {
                float* d = Ab2 + asto[j];
                d[0] = __uint_as_float(f2tf32(sa[j].x));
                d[1] = __uint_as_float(f2tf32(sa[j].y));
                d[2] = __uint_as_float(f2tf32(sa[j].z));
                d[3] = __uint_as_float(f2tf32(sa[j].w));
            }
#pragma unroll
            for (int j = 0; j < 4; j++) {
                float* d = Bb2 + bsto[j];
                d[0] = __uint_as_float(f2tf32(sb[j].x));
                d[1] = __uint_as_float(f2tf32(sb[j].y));
                d[2] = __uint_as_float(f2tf32(sb[j].z));
                d[3] = __uint_as_float(f2tf32(sb[j].w));
            }
        }
        __syncthreads();
    }

    // epilogue
#pragma unroll
    for (int mi = 0; mi < 4; mi++) {
        int r0 = row0 + wm + mi * 16 + (lane >> 2);
        int r1 = r0 + 8;
#pragma unroll
        for (int ni = 0; ni < 4; ni++) {
            int c = col0 + wn + ni * 8 + (lane & 3) * 2;
            if (!fuseCombine) {
                if (r0 < M) {
                    float* p = C + (size_t)(base + r0) * N + c;
                    p[0] = acc[mi][ni][0]; p[1] = acc[mi][ni][1];
                }
                if (r1 < M) {
                    float* p = C + (size_t)(base + r1) * N + c;
                    p[0] = acc[mi][ni][2]; p[1] = acc[mi][ni][3];
                }
            } else {
                if (r0 < M) {
                    int t = r0;
                    float w0 = g_topk_w[2 * t], w1 = g_topk_w[2 * t + 1];
                    int   s0 = g_slot_of[2 * t], s1 = g_slot_of[2 * t + 1];
                    float sg = g_sig[t];
                    float2 y0 = *(const float2*)&g_y[(size_t)s0 * HID + c];
                    float2 y1 = *(const float2*)&g_y[(size_t)s1 * HID + c];
                    float* p = C + (size_t)t * N + c;
                    p[0] = w0 * y0.x + w1 * y1.x + sg * acc[mi][ni][0];
                    p[1] = w0 * y0.y + w1 * y1.y + sg * acc[mi][ni][1];
                }
                if (r1 < M) {
                    int t = r1;
                    float w0 = g_topk_w[2 * t], w1 = g_topk_w[2 * t + 1];
                    int   s0 = g_slot_of[2 * t], s1 = g_slot_of[2 * t + 1];
                    float sg = g_sig[t];
                    float2 y0 = *(const float2*)&g_y[(size_t)s0 * HID + c];
                    float2 y1 = *(const float2*)&g_y[(size_t)s1 * HID + c];
                    float* p = C + (size_t)t * N + c;
                    p[0] = w0 * y0.x + w1 * y1.x + sg * acc[mi][ni][2];
                    p[1] = w0 * y0.y + w1 * y1.y + sg * acc[mi][ni][3];
                }
            }
        }
    }
}

// ---------------------------------------------------------------------------
// launch
// ---------------------------------------------------------------------------
extern "C" void kernel_launch(void* const* d_in, const int* in_sizes, int n_in,
                              void* d_out, int out_size)
{
    const float* x     = (const float*)d_in[0];
    const float* gate  = (const float*)d_in[1];
    const float* w1    = (const float*)d_in[2];
    const float* w2    = (const float*)d_in[3];
    const float* w3    = (const float*)d_in[4];
    const float* sw1   = (const float*)d_in[5];
    const float* sw2   = (const float*)d_in[6];
    const float* sw3   = (const float*)d_in[7];
    const float* sgate = (const float*)d_in[8];
    float* out = (float*)d_out;

    float* logits = nullptr;
    if ((size_t)out_size >= (size_t)T_TOK * HID + (size_t)T_TOK * NEXP)
        logits = out + (size_t)T_TOK * HID;

    float *bufA, *bufB, *ybuf;
    cudaGetSymbolAddress((void**)&bufA, g_bufA);
    cudaGetSymbolAddress((void**)&bufB, g_bufB);
    cudaGetSymbolAddress((void**)&ybuf, g_y);

    static int smem_set = 0;
    if (!smem_set) {
        cudaFuncSetAttribute(dual_swiglu_kernel,
                             cudaFuncAttributeMaxDynamicSharedMemorySize, DUAL_SMEM);
        cudaFuncSetAttribute(sgemm_tc_kernel,
                             cudaFuncAttributeMaxDynamicSharedMemorySize, SG_SMEM);
        smem_set = 1;
    }

    init_kernel<<<1, 32>>>();
    router_kernel<<<T_TOK / 8, 256>>>(x, gate, sgate, logits);
    prefix_kernel<<<1, 32>>>();
    scatter_kernel<<<T_TOK / 256, 256>>>();

    // Stage A merged: z=0..7 MoE experts -> bufA, z=8..9 shared halves -> bufB
    dual_swiglu_kernel<<<dim3(16, T_TOK / 128, NEXP + 2), 256, DUAL_SMEM>>>(
        x, w1, w3, bufA, sw1, sw3, bufB);

    // MoE stage B: y_slot = h @ w2[e]
    sgemm_tc_kernel<<<dim3(HID / 128, T_TOK / 128, NEXP), 256, SG_SMEM>>>(
        bufA, w2, ybuf, HID, MOEI, (long)MOEI * HID, 0, 1, 0, 0);

    // Shared stage B with fused final combine -> out
    sgemm_tc_kernel<<<dim3(HID / 128, T_TOK / 128, 1), 256, SG_SMEM>>>(
        bufB, sw2, out, HID, SHI, 0L, T_TOK, 0, 0, 1);
}